// round 8
// baseline (speedup 1.0000x reference)
#include <cuda_runtime.h>
#include <math.h>
#include <stdint.h>

// ---------------- problem constants ----------------
#define DIMX   96
#define HIDX   384
#define DEPTHX 5
#define HEADSX 8
#define INNERX 6144          // 64 * 96
#define DHX    768           // INNERX / HEADSX
#define BX     2
#define NSEQ   512
#define ROWSX  (BX*NSEQ)     // 1024
#define NQKV   (3*INNERX)    // 18432
#define SCALEX 0.125f
#define EPSX   1e-5f
#define SPLIT_WO 16
#define SPLIT_W2 4
#define STAGES 4
#define AS_STRIDE 2048       // floats per A stage: 128 rows * 16
#define BS_STRIDE 2176       // floats per B stage: max(16*136, 128*16)
#define SMEM_BYTES (STAGES*(AS_STRIDE+BS_STRIDE)*4)   // 67584

// permutation helpers:
// p16: logical col c -> storage pos within 16-group: 4*(c%4) + (c%16)/4
#define P16(c) (((c) & ~15) | ((((c) & 3) << 2) | (((c) & 15) >> 2)))
// p32: logical col c -> storage pos within 32-group: 4*(c%8) + (c%32)/8
#define P32(c) (((c) & ~31) | ((((c) & 7) << 2) | (((c) & 31) >> 3)))
// inverse of p32 (for gather packs): storage s -> logical
#define IP32(s) (((s) & ~31) | ((((s) & 3) << 3) | (((s) & 31) >> 2)))

// ---------------- scratch (device globals; no allocation allowed) ----------------
__device__ float g_x   [ROWSX*DIMX];
__device__ float g_h   [ROWSX*DIMX];           // p16 cols
__device__ float g_qkv [ROWSX*NQKV];           // q,k: p16 cols; v: p32 cols
__device__ float g_o   [ROWSX*INNERX];         // p16 cols
__device__ float g_sim [BX*HEADSX*NSEQ*NSEQ];  // p16 cols
__device__ float g_mh  [ROWSX*HIDX];           // p16 cols
__device__ float g_part[SPLIT_WO*ROWSX*DIMX];  // plain
// pre-rounded (tf32-rna) weights, n-cols p32
__device__ float g_wqkv[15*DIMX*NQKV];
__device__ float g_wo  [15*INNERX*DIMX];
__device__ float g_w1  [10*DIMX*HIDX];
__device__ float g_w2  [10*HIDX*DIMX];

// ---------------- helpers ----------------
__device__ __forceinline__ float to_tf32(float f) {
    uint32_t o;
    asm("cvt.rna.tf32.f32 %0, %1;" : "=r"(o) : "f"(f));
    return __uint_as_float(o);
}
__device__ __forceinline__ void cp16(uint32_t smem_addr, const float* gptr, bool pred) {
    int sz = pred ? 16 : 0;
    asm volatile("cp.async.cg.shared.global [%0], [%1], 16, %2;\n"
                 :: "r"(smem_addr), "l"(gptr), "r"(sz));
}
__device__ __forceinline__ void cp_commit() { asm volatile("cp.async.commit_group;\n"); }
template<int N>
__device__ __forceinline__ void cp_wait() { asm volatile("cp.async.wait_group %0;\n" :: "n"(N)); }

__device__ __forceinline__ void mma_tf32(float& d0, float& d1, float& d2, float& d3,
                                         float a0, float a1, float a2, float a3,
                                         float b0, float b1) {
    asm volatile(
        "mma.sync.aligned.m16n8k8.row.col.f32.tf32.tf32.f32 "
        "{%0,%1,%2,%3}, {%4,%5,%6,%7}, {%8,%9}, {%0,%1,%2,%3};\n"
        : "+f"(d0), "+f"(d1), "+f"(d2), "+f"(d3)
        : "r"(__float_as_uint(a0)), "r"(__float_as_uint(a1)),
          "r"(__float_as_uint(a2)), "r"(__float_as_uint(a3)),
          "r"(__float_as_uint(b0)), "r"(__float_as_uint(b1)));
}

// ---------------- weight packing (p32 cols, RNA-rounded) ----------------
__global__ void pack_qkv_kernel(const float* __restrict__ Wq, const float* __restrict__ Wk,
                                const float* __restrict__ Wv, float* __restrict__ dst, int n) {
    int i = blockIdx.x * 256 + threadIdx.x;
    if (i >= n) return;
    int c  = i % NQKV;
    int lk = i / NQKV;
    int o  = IP32(c);                 // logical column in packed [Wq|Wk|Wv]
    float v;
    if (o < INNERX)           v = Wq[(size_t)lk * INNERX + o];
    else if (o < 2*INNERX)    v = Wk[(size_t)lk * INNERX + (o - INNERX)];
    else                      v = Wv[(size_t)lk * INNERX + (o - 2*INNERX)];
    dst[i] = to_tf32(v);
}
// generic p32-col gather pack:  dst[r][c] = rna(src[r][ip32(c)]),  ld = N
__global__ void pack_p32_kernel(const float* __restrict__ src, float* __restrict__ dst,
                                int N, int n) {
    int i = blockIdx.x * 256 + threadIdx.x;
    if (i >= n) return;
    int c = i % N;
    int r = i / N;
    dst[i] = to_tf32(src[(size_t)r * N + IP32(c)]);
}
__global__ void copy_kernel(const float* __restrict__ src, float* __restrict__ dst, int n) {
    int i = blockIdx.x * 256 + threadIdx.x;
    if (i < n) dst[i] = src[i];
}

// ---------------- LayerNorm (dim=96): writes h with p16 cols ----------------
__global__ void ln_kernel(const float* __restrict__ in, const float* __restrict__ g,
                          float* __restrict__ out) {
    int row = blockIdx.x;
    int t   = threadIdx.x;
    __shared__ float s[DIMX];
    __shared__ float red[2];
    float v = in[(size_t)row*DIMX + t];
    s[t] = v;
    __syncthreads();
    float a = 0.f;
    if (t < 32) a = s[t] + s[t+32] + s[t+64];
    #pragma unroll
    for (int o = 16; o > 0; o >>= 1) a += __shfl_down_sync(0xffffffffu, a, o);
    if (t == 0) red[0] = a;
    __syncthreads();
    float mu = red[0] * (1.0f / DIMX);
    float d  = v - mu;
    s[t] = d * d;
    __syncthreads();
    float b = 0.f;
    if (t < 32) b = s[t] + s[t+32] + s[t+64];
    #pragma unroll
    for (int o = 16; o > 0; o >>= 1) b += __shfl_down_sync(0xffffffffu, b, o);
    if (t == 0) red[1] = b;
    __syncthreads();
    float var = red[1] * (1.0f / DIMX);
    float r = to_tf32(d * rsqrtf(var + EPSX) * (g[t] + 1.0f));
    out[(size_t)row*DIMX + P16(t)] = r;
}

// ---------------- fused split-K reduce + residual + LayerNorm ----------------
// val = x + [bias] + sum(part). REPLACE: x = ln (plain).
// else: x = val (plain); out[...] = ln  (PERMOUT: p16+rna for h; else plain for d_out)
template<bool PERMOUT, bool REPLACE, bool HASBIAS>
__global__ void red_ln_kernel(const float* __restrict__ part, int S,
                              const float* __restrict__ bias,
                              float* __restrict__ x, const float* __restrict__ g,
                              float* __restrict__ out) {
    const int MN = ROWSX * DIMX;
    int row = blockIdx.x;
    int t   = threadIdx.x;
    size_t idx = (size_t)row*DIMX + t;
    float val = x[idx];
    if (HASBIAS) val += bias[t];
    for (int s = 0; s < S; s++) val += part[(size_t)s*MN + idx];
    __shared__ float sm[DIMX];
    __shared__ float red[2];
    sm[t] = val;
    __syncthreads();
    float a = 0.f;
    if (t < 32) a = sm[t] + sm[t+32] + sm[t+64];
    #pragma unroll
    for (int o = 16; o > 0; o >>= 1) a += __shfl_down_sync(0xffffffffu, a, o);
    if (t == 0) red[0] = a;
    __syncthreads();
    float mu = red[0] * (1.0f / DIMX);
    float d  = val - mu;
    sm[t] = d * d;
    __syncthreads();
    float b = 0.f;
    if (t < 32) b = sm[t] + sm[t+32] + sm[t+64];
    #pragma unroll
    for (int o = 16; o > 0; o >>= 1) b += __shfl_down_sync(0xffffffffu, b, o);
    if (t == 0) red[1] = b;
    __syncthreads();
    float var = red[1] * (1.0f / DIMX);
    float lnv = d * rsqrtf(var + EPSX) * (g[t] + 1.0f);
    if (REPLACE) {
        x[idx] = lnv;
    } else {
        x[idx] = val;
        if (PERMOUT) out[(size_t)row*DIMX + P16(t)] = to_tf32(lnv);
        else         out[idx] = lnv;
    }
}

// ---------------- row softmax (permutation-invariant; in-place; rna out) ----------------
__global__ void softmax_kernel(float* __restrict__ sim) {
    int row = blockIdx.x;
    float* p = sim + (size_t)row * NSEQ;
    int t = threadIdx.x;                    // 256
    float a = p[t], b = p[t + 256];
    __shared__ float s[256];
    s[t] = fmaxf(a, b);
    __syncthreads();
    for (int o = 128; o >= 32; o >>= 1) { if (t < o) s[t] = fmaxf(s[t], s[t+o]); __syncthreads(); }
    if (t < 32) {
        float x = s[t];
        #pragma unroll
        for (int o = 16; o > 0; o >>= 1) x = fmaxf(x, __shfl_down_sync(0xffffffffu, x, o));
        if (t == 0) s[0] = x;
    }
    __syncthreads();
    float m = s[0];
    __syncthreads();
    float ea = expf(a - m), eb = expf(b - m);
    s[t] = ea + eb;
    __syncthreads();
    for (int o = 128; o >= 32; o >>= 1) { if (t < o) s[t] += s[t+o]; __syncthreads(); }
    if (t < 32) {
        float x = s[t];
        #pragma unroll
        for (int o = 16; o > 0; o >>= 1) x += __shfl_down_sync(0xffffffffu, x, o);
        if (t == 0) s[0] = x;
    }
    __syncthreads();
    float inv = 1.0f / s[0];
    p[t]       = to_tf32(ea * inv);
    p[t + 256] = to_tf32(eb * inv);
}

// ---------------- tf32 tensor-core GEMM, 4-stage cp.async, vectorized frags ----------------
// 128x128 block tile, BK=16, 256 threads, warp tile 64x32.
// A global: row-major [M,K] with K-cols p16-permuted.
// B global: NN [K,N] rows plain / N-cols p32-permuted; TRANSB [N,K] K-cols p16.
// OPERM: 0 = plain C cols, 1 = p16, 3 = qkv-mixed (p16 if n<2*INNERX else p32)
template<bool TRANSB, bool BIAS, bool GELU, bool SPLIT, bool ROUND, int OPERM>
__global__ __launch_bounds__(256, 2)
void mma_gemm(const float* __restrict__ A, const float* __restrict__ Bm,
              const float* __restrict__ bias, float* __restrict__ C,
              int M, int Nn, int K_len,
              int lda, int ldb, int ldc,
              long sA_b, long sA_h, long sB_b, long sB_h, long sC_b, long sC_h,
              long splitStride, float alpha) {
    extern __shared__ float smem[];
    float* Asm = smem;                         // [STAGES][128][16]
    float* Bsm = smem + STAGES*AS_STRIDE;      // NN: [16][136]; TRANSB: [128][16]

    const int tid = threadIdx.x;
    const int bz  = blockIdx.z;
    const float* Ab; const float* Bb; float* Cb;
    int kbase;
    if (SPLIT) {
        Ab = A; Bb = Bm;
        Cb = C + (long)bz * splitStride;
        kbase = bz * K_len;
    } else {
        long bb = bz >> 3, hh = bz & 7;
        Ab = A  + bb * sA_b + hh * sA_h;
        Bb = Bm + bb * sB_b + hh * sB_h;
        Cb = C  + bb * sC_b + hh * sC_h;
        kbase = 0;
    }

    const int bm = blockIdx.y * 128;
    const int bn = blockIdx.x * 128;
    const int wid = tid >> 5;
    const int lane = tid & 31;
    const int gid = lane >> 2;
    const int tg  = lane & 3;
    const int wm = (wid & 1) * 64;
    const int wn = (wid >> 1) * 32;

    const uint32_t as0 = (uint32_t)__cvta_generic_to_shared(Asm);
    const uint32_t bs0 = (uint32_t)__cvta_generic_to_shared(Bsm);

    const int a_row0 = tid >> 2;               // 0..63
    const int a_kc   = (tid & 3) * 4;
    const int bn_k0  = tid >> 5;               // 0..7
    const int bn_nc  = (tid & 31) * 4;

    const int nt = K_len / 16;

    float acc[4][4][4];
    #pragma unroll
    for (int mi = 0; mi < 4; mi++)
        #pragma unroll
        for (int ni = 0; ni < 4; ni++)
            #pragma unroll
            for (int r = 0; r < 4; r++) acc[mi][ni][r] = 0.f;

    auto load_tile = [&](int t, int s) {
        const int kpos = kbase + t * 16;
        #pragma unroll
        for (int r = 0; r < 2; r++) {
            int row = a_row0 + 64 * r;
            const float* src = Ab + (size_t)(bm + row) * lda + kpos + a_kc;
            cp16(as0 + (s * AS_STRIDE + row * 16 + a_kc) * 4, src, (bm + row) < M);
        }
        if (!TRANSB) {
            #pragma unroll
            for (int r = 0; r < 2; r++) {
                int krow = bn_k0 + 8 * r;
                const float* src = Bb + (size_t)(kpos + krow) * ldb + bn + bn_nc;
                cp16(bs0 + (s * BS_STRIDE + krow * 136 + bn_nc) * 4, src, (bn + bn_nc) < Nn);
            }
        } else {
            #pragma unroll
            for (int r = 0; r < 2; r++) {
                int nrow = a_row0 + 64 * r;
                const float* src = Bb + (size_t)(bn + nrow) * ldb + kpos + a_kc;
                cp16(bs0 + (s * BS_STRIDE + nrow * 16 + a_kc) * 4, src, (bn + nrow) < Nn);
            }
        }
        cp_commit();
    };

    #pragma unroll
    for (int s = 0; s < STAGES - 1; s++)
        if (s < nt) load_tile(s, s);

    for (int t = 0; t < nt; t++) {
        const int cur = t & 3;
        if (t + 3 <= nt)      cp_wait<2>();
        else if (t + 2 <= nt) cp_wait<1>();
        else                  cp_wait<0>();
        __syncthreads();
        if (t + 3 < nt) load_tile(t + 3, (t + 3) & 3);

        const float* as = Asm + cur * AS_STRIDE;
        const float* bs = Bsm + cur * BS_STRIDE;

        // ---- B fragments: bb[slot][ni]; slots: ks0-b0, ks0-b1, ks8-b0, ks8-b1
        float bb[4][4];
        if (!TRANSB) {
            #pragma unroll
            for (int j = 0; j < 4; j++) {
                float4 u = *(const float4*)(bs + (tg + 4*j) * 136 + wn + gid * 4);
                bb[j][0] = u.x; bb[j][1] = u.y; bb[j][2] = u.z; bb[j][3] = u.w;
            }
        } else {
            #pragma unroll
            for (int ni = 0; ni < 4; ni++) {
                float4 u = *(const float4*)(bs + (wn + ni*8 + gid) * 16 + tg * 4);
                bb[0][ni] = u.x; bb[1][ni] = u.y; bb[2][ni] = u.z; bb[3][ni] = u.w;
            }
        }
        // ---- A fragments per mi + MMAs
        #pragma unroll
        for (int mi = 0; mi < 4; mi++) {
            int mrow = wm + mi * 16 + gid;
            float4 v0 = *(const float4*)(as + mrow * 16 + tg * 4);        // k=tg,tg+4,tg+8,tg+12 (row)
            float4 v1 = *(const float4*)(as + (mrow + 8) * 16 + tg * 4);  // (row+8)
            #pragma unroll
            for (int ni = 0; ni < 4; ni++)
                mma_tf32(acc[mi][ni][0], acc[mi][ni][1], acc[mi][ni][2], acc[mi][ni][3],
                         v0.x, v1.x, v0.y, v1.y, bb[0][ni], bb[1][ni]);
            #pragma unroll
            for (int ni = 0; ni < 4; ni++)
                mma_tf32(acc[mi][ni][0], acc[mi][ni][1], acc[mi][ni][2], acc[mi][ni][3],
                         v0.z, v1.z, v0.w, v1.w, bb[2][ni], bb[3][ni]);
        }
    }
    // ensure smem reads done before (potential) reuse — kernel ends, but sync for safety of tail warps
    __syncthreads();

    // ---- epilogue (logical n; remap store column per OPERM)
    #pragma unroll
    for (int mi = 0; mi < 4; mi++) {
        int m0 = bm + wm + mi * 16 + gid;
        #pragma unroll
        for (int ni = 0; ni < 4; ni++) {
            int n0 = bn + wn + ni * 8 + tg * 2;
            #pragma unroll
            for (int rr = 0; rr < 2; rr++) {
                int m = m0 + rr * 8;
                #pragma unroll
                for (int cc = 0; cc < 2; cc++) {
                    int n = n0 + cc;
                    if (n < Nn) {
                        float v = acc[mi][ni][rr * 2 + cc] * alpha;
                        if (BIAS) v += bias[n];
                        if (GELU) v = 0.5f * v * (1.0f + erff(v * 0.70710678118654752f));
                        if (ROUND) v = to_tf32(v);
                        int ns;
                        if (OPERM == 1)      ns = P16(n);
                        else if (OPERM == 3) ns = (n < 2*INNERX) ? P16(n) : P32(n);
                        else                 ns = n;
                        Cb[(size_t)m * ldc + ns] = v;
                    }
                }
            }
        }
    }
}

// ---------------- host orchestration ----------------
extern "C" void kernel_launch(void* const* d_in, const int* in_sizes, int n_in,
                              void* d_out, int out_size) {
    const float* x         = (const float*)d_in[0];
    const float* gam_a     = (const float*)d_in[1];
    const float* Wq        = (const float*)d_in[2];
    const float* Wk        = (const float*)d_in[3];
    const float* Wv        = (const float*)d_in[4];
    const float* Wo        = (const float*)d_in[5];
    const float* gam_m     = (const float*)d_in[6];
    const float* W1        = (const float*)d_in[7];
    const float* b1        = (const float*)d_in[8];
    const float* W2        = (const float*)d_in[9];
    const float* b2        = (const float*)d_in[10];
    const float* gam_mid   = (const float*)d_in[11];
    const float* gam_final = (const float*)d_in[12];
    float* out = (float*)d_out;

    float *px, *ph, *pqkv, *po, *psim, *pmh, *ppart, *pwqkv, *pwo, *pw1, *pw2;
    cudaGetSymbolAddress((void**)&px,    g_x);
    cudaGetSymbolAddress((void**)&ph,    g_h);
    cudaGetSymbolAddress((void**)&pqkv,  g_qkv);
    cudaGetSymbolAddress((void**)&po,    g_o);
    cudaGetSymbolAddress((void**)&psim,  g_sim);
    cudaGetSymbolAddress((void**)&pmh,   g_mh);
    cudaGetSymbolAddress((void**)&ppart, g_part);
    cudaGetSymbolAddress((void**)&pwqkv, g_wqkv);
    cudaGetSymbolAddress((void**)&pwo,   g_wo);
    cudaGetSymbolAddress((void**)&pw1,   g_w1);
    cudaGetSymbolAddress((void**)&pw2,   g_w2);

    cudaFuncSetAttribute(mma_gemm<false,false,false,false,true,3>,
                         cudaFuncAttributeMaxDynamicSharedMemorySize, SMEM_BYTES);
    cudaFuncSetAttribute(mma_gemm<true,false,false,false,false,1>,
                         cudaFuncAttributeMaxDynamicSharedMemorySize, SMEM_BYTES);
    cudaFuncSetAttribute(mma_gemm<false,false,false,false,true,1>,
                         cudaFuncAttributeMaxDynamicSharedMemorySize, SMEM_BYTES);
    cudaFuncSetAttribute(mma_gemm<false,false,false,true,false,0>,
                         cudaFuncAttributeMaxDynamicSharedMemorySize, SMEM_BYTES);
    cudaFuncSetAttribute(mma_gemm<false,true,true,false,true,1>,
                         cudaFuncAttributeMaxDynamicSharedMemorySize, SMEM_BYTES);

    // ---- weight packing (p32 cols, RNA) ----
    {
        int nq = 15*DIMX*NQKV;
        pack_qkv_kernel<<<(nq + 255)/256, 256>>>(Wq, Wk, Wv, pwqkv, nq);
        int no = 15*INNERX*DIMX;
        pack_p32_kernel<<<(no + 255)/256, 256>>>(Wo, pwo, DIMX, no);
        int n1 = 10*DIMX*HIDX;
        pack_p32_kernel<<<(n1 + 255)/256, 256>>>(W1, pw1, HIDX, n1);
        int n2 = 10*HIDX*DIMX;
        pack_p32_kernel<<<(n2 + 255)/256, 256>>>(W2, pw2, DIMX, n2);
    }

    copy_kernel<<<(ROWSX*DIMX + 255)/256, 256>>>(x, px, ROWSX*DIMX);
    ln_kernel<<<ROWSX, DIMX>>>(px, gam_a + 0, ph);

    const long sQKV_b = (long)NSEQ * NQKV;
    const long sQKV_h = DHX;
    const long sSIM_h = (long)NSEQ * NSEQ;
    const long sSIM_b = sSIM_h * HEADSX;
    const long sO_b   = (long)NSEQ * INNERX;
    const long sO_h   = DHX;

    auto do_attn = [&](int widx) {
        const float* wqkv_l = pwqkv + (size_t)widx * DIMX * NQKV;
        const float* wo_l   = pwo   + (size_t)widx * INNERX * DIMX;
        // fused QKV: q,k out p16; v out p32
        mma_gemm<false,false,false,false,true,3><<<dim3(NQKV/128, ROWSX/128, 1), 256, SMEM_BYTES>>>(
            ph, wqkv_l, nullptr, pqkv, ROWSX, NQKV, DIMX, DIMX, NQKV, NQKV,
            0,0,0,0,0,0, 0, 1.0f);
        // scores = SCALE * q @ k^T  (sim cols p16)
        mma_gemm<true,false,false,false,false,1><<<dim3(NSEQ/128, NSEQ/128, BX*HEADSX), 256, SMEM_BYTES>>>(
            pqkv, pqkv + INNERX, nullptr, psim, NSEQ, NSEQ, DHX, NQKV, NQKV, NSEQ,
            sQKV_b, sQKV_h, sQKV_b, sQKV_h, sSIM_b, sSIM_h, 0, SCALEX);
        softmax_kernel<<<BX*HEADSX*NSEQ, 256>>>(psim);
        // context = a @ v  (o cols p16)
        mma_gemm<false,false,false,false,true,1><<<dim3(DHX/128, NSEQ/128, BX*HEADSX), 256, SMEM_BYTES>>>(
            psim, pqkv + 2*INNERX, nullptr, po, NSEQ, DHX, NSEQ, NSEQ, NQKV, INNERX,
            sSIM_b, sSIM_h, sQKV_b, sQKV_h, sO_b, sO_h, 0, 1.0f);
        // Wo split-K partials (plain cols)
        mma_gemm<false,false,false,true,false,0><<<dim3(1, ROWSX/128, SPLIT_WO), 256, SMEM_BYTES>>>(
            po, wo_l, nullptr, ppart, ROWSX, DIMX, INNERX/SPLIT_WO, INNERX, DIMX, DIMX,
            0,0,0,0,0,0, (long)ROWSX*DIMX, 1.0f);
    };
    auto do_mlp_gemms = [&](int midx) {
        const float* w1_l = pw1 + (size_t)midx * DIMX * HIDX;
        const float* w2_l = pw2 + (size_t)midx * HIDX * DIMX;
        mma_gemm<false,true,true,false,true,1><<<dim3(HIDX/128, ROWSX/128, 1), 256, SMEM_BYTES>>>(
            ph, w1_l, b1 + (size_t)midx * HIDX, pmh, ROWSX, HIDX, DIMX, DIMX, HIDX, HIDX,
            0,0,0,0,0,0, 0, 1.0f);
        mma_gemm<false,false,false,true,false,0><<<dim3(1, ROWSX/128, SPLIT_W2), 256, SMEM_BYTES>>>(
            pmh, w2_l, nullptr, ppart, ROWSX, DIMX, HIDX/SPLIT_W2, HIDX, DIMX, DIMX,
            0,0,0,0,0,0, (long)ROWSX*DIMX, 1.0f);
    };

    for (int d = 0; d < DEPTHX; d++) {
        do_attn(3*d + 0);
        red_ln_kernel<true,false,false><<<ROWSX, DIMX>>>(
            ppart, SPLIT_WO, nullptr, px, gam_m + (size_t)(2*d+0)*DIMX, ph);
        do_mlp_gemms(2*d + 0);
        red_ln_kernel<true,false,true><<<ROWSX, DIMX>>>(
            ppart, SPLIT_W2, b2 + (size_t)(2*d+0)*DIMX, px, gam_a + (size_t)(3*d+1)*DIMX, ph);
        do_attn(3*d + 1);
        red_ln_kernel<true,false,false><<<ROWSX, DIMX>>>(
            ppart, SPLIT_WO, nullptr, px, gam_a + (size_t)(3*d+2)*DIMX, ph);
        do_attn(3*d + 2);
        red_ln_kernel<false,true,false><<<ROWSX, DIMX>>>(
            ppart, SPLIT_WO, nullptr, px, gam_mid + (size_t)d*DIMX, px);
        ln_kernel<<<ROWSX, DIMX>>>(px, gam_m + (size_t)(2*d+1)*DIMX, ph);
        do_mlp_gemms(2*d + 1);
        if (d < DEPTHX - 1) {
            red_ln_kernel<true,false,true><<<ROWSX, DIMX>>>(
                ppart, SPLIT_W2, b2 + (size_t)(2*d+1)*DIMX, px, gam_a + (size_t)(3*d+3)*DIMX, ph);
        } else {
            red_ln_kernel<false,false,true><<<ROWSX, DIMX>>>(
                ppart, SPLIT_W2, b2 + (size_t)(2*d+1)*DIMX, px, gam_final, out);
        }
    }
}

// round 9
// speedup vs baseline: 1.4864x; 1.4864x over previous
#include <cuda_runtime.h>
#include <cuda_bf16.h>
#include <math.h>
#include <stdint.h>

// ---------------- problem constants ----------------
#define DIMX   96
#define HIDX   384
#define DEPTHX 5
#define HEADSX 8
#define INNERX 6144          // 64 * 96
#define DHX    768           // INNERX / HEADSX
#define BX     2
#define NSEQ   512
#define ROWSX  (BX*NSEQ)     // 1024
#define NQKV   (3*INNERX)    // 18432
#define SCALEX 0.125f
#define EPSX   1e-5f
#define SPLIT_WO 16
#define SPLIT_W2 4
#define STAGES 4
#define A_STG 5120           // bf16 per A stage: 128 rows * 40
#define B_STG 5120           // bf16 per B stage (TRANSB 128*40; NN uses 16*136 words < this)
#define B_STGW 2560          // words per B stage
#define SMEM_BYTES (STAGES*(A_STG+B_STG)*2)   // 81920

typedef __nv_bfloat16 bf16;

// ---------------- scratch (device globals; no allocation allowed) ----------------
__device__ float g_x   [ROWSX*DIMX];
__device__ bf16  g_h   [ROWSX*DIMX];
__device__ bf16  g_qk  [ROWSX*2*INNERX];           // q | k, ld = 2*INNERX
__device__ uint32_t g_v[(ROWSX/2)*INNERX];         // v pair-interleaved [m/2][c] words
__device__ bf16  g_o   [ROWSX*INNERX];
__device__ bf16  g_sim [BX*HEADSX*NSEQ*NSEQ];
__device__ bf16  g_mh  [ROWSX*HIDX];
__device__ float g_part[SPLIT_WO*ROWSX*DIMX];
// weights: NN-B pair-interleaved words [L][K/2][N]
__device__ uint32_t g_wqkv[15*(DIMX/2)*NQKV];
__device__ uint32_t g_wo  [15*(INNERX/2)*DIMX];
__device__ uint32_t g_w1  [10*(DIMX/2)*HIDX];
__device__ uint32_t g_w2  [10*(HIDX/2)*DIMX];

// ---------------- helpers ----------------
__device__ __forceinline__ void cp16(uint32_t smem_addr, const void* gptr, bool pred) {
    int sz = pred ? 16 : 0;
    asm volatile("cp.async.cg.shared.global [%0], [%1], 16, %2;\n"
                 :: "r"(smem_addr), "l"(gptr), "r"(sz));
}
__device__ __forceinline__ void cp_commit() { asm volatile("cp.async.commit_group;\n"); }
template<int N>
__device__ __forceinline__ void cp_wait() { asm volatile("cp.async.wait_group %0;\n" :: "n"(N)); }

__device__ __forceinline__ void mma_bf16(float& d0, float& d1, float& d2, float& d3,
                                         uint32_t a0, uint32_t a1, uint32_t a2, uint32_t a3,
                                         uint32_t b0, uint32_t b1) {
    asm volatile(
        "mma.sync.aligned.m16n8k16.row.col.f32.bf16.bf16.f32 "
        "{%0,%1,%2,%3}, {%4,%5,%6,%7}, {%8,%9}, {%0,%1,%2,%3};\n"
        : "+f"(d0), "+f"(d1), "+f"(d2), "+f"(d3)
        : "r"(a0), "r"(a1), "r"(a2), "r"(a3), "r"(b0), "r"(b1));
}

__device__ __forceinline__ uint32_t pack2(float lo, float hi) {
    __nv_bfloat162 p = __floats2bfloat162_rn(lo, hi);   // x=lo (low half), y=hi
    return *(uint32_t*)&p;
}

// ---------------- weight packing ----------------
// generic: src fp32 [L*K, N] -> dst words [L*K/2, N]; word w holds (row 2*(w/N), 2*(w/N)+1) col w%N
__global__ void pack_pairs_kernel(const float* __restrict__ src, uint32_t* __restrict__ dst,
                                  int N, int nwords) {
    int w = blockIdx.x * 256 + threadIdx.x;
    if (w >= nwords) return;
    int n   = w % N;
    int lkp = w / N;
    size_t r0 = (size_t)(2*lkp) * N + n;
    dst[w] = pack2(src[r0], src[r0 + N]);
}
// qkv: three [15*96, INNER] sources -> [15*48, NQKV] words, cols [Wq|Wk|Wv]
__global__ void pack_qkv_kernel(const float* __restrict__ Wq, const float* __restrict__ Wk,
                                const float* __restrict__ Wv, uint32_t* __restrict__ dst, int nwords) {
    int w = blockIdx.x * 256 + threadIdx.x;
    if (w >= nwords) return;
    int n   = w % NQKV;
    int lkp = w / NQKV;
    int row0 = 2 * lkp;
    const float* S; int c;
    if (n < INNERX)            { S = Wq; c = n; }
    else if (n < 2*INNERX)     { S = Wk; c = n - INNERX; }
    else                       { S = Wv; c = n - 2*INNERX; }
    size_t r0 = (size_t)row0 * INNERX + c;
    dst[w] = pack2(S[r0], S[r0 + INNERX]);
}
__global__ void copy_kernel(const float* __restrict__ src, float* __restrict__ dst, int n) {
    int i = blockIdx.x * 256 + threadIdx.x;
    if (i < n) dst[i] = src[i];
}

// ---------------- LayerNorm (dim=96) -> bf16 h ----------------
__global__ void ln_kernel(const float* __restrict__ in, const float* __restrict__ g,
                          bf16* __restrict__ out) {
    int row = blockIdx.x;
    int t   = threadIdx.x;
    __shared__ float s[DIMX];
    __shared__ float red[2];
    float v = in[(size_t)row*DIMX + t];
    s[t] = v;
    __syncthreads();
    float a = 0.f;
    if (t < 32) a = s[t] + s[t+32] + s[t+64];
    #pragma unroll
    for (int o = 16; o > 0; o >>= 1) a += __shfl_down_sync(0xffffffffu, a, o);
    if (t == 0) red[0] = a;
    __syncthreads();
    float mu = red[0] * (1.0f / DIMX);
    float d  = v - mu;
    s[t] = d * d;
    __syncthreads();
    float b = 0.f;
    if (t < 32) b = s[t] + s[t+32] + s[t+64];
    #pragma unroll
    for (int o = 16; o > 0; o >>= 1) b += __shfl_down_sync(0xffffffffu, b, o);
    if (t == 0) red[1] = b;
    __syncthreads();
    float var = red[1] * (1.0f / DIMX);
    out[(size_t)row*DIMX + t] = __float2bfloat16_rn(d * rsqrtf(var + EPSX) * (g[t] + 1.0f));
}

// ---------------- fused split-K reduce + residual + LayerNorm ----------------
// val = x + [bias] + sum(part). REPLACE: x = ln (fp32). else: x = val; out = ln (bf16 or fp32).
template<bool BFOUT, bool REPLACE, bool HASBIAS>
__global__ void red_ln_kernel(const float* __restrict__ part, int S,
                              const float* __restrict__ bias,
                              float* __restrict__ x, const float* __restrict__ g,
                              void* __restrict__ outp) {
    const int MN = ROWSX * DIMX;
    int row = blockIdx.x;
    int t   = threadIdx.x;
    size_t idx = (size_t)row*DIMX + t;
    float val = x[idx];
    if (HASBIAS) val += bias[t];
    for (int s = 0; s < S; s++) val += part[(size_t)s*MN + idx];
    __shared__ float sm[DIMX];
    __shared__ float red[2];
    sm[t] = val;
    __syncthreads();
    float a = 0.f;
    if (t < 32) a = sm[t] + sm[t+32] + sm[t+64];
    #pragma unroll
    for (int o = 16; o > 0; o >>= 1) a += __shfl_down_sync(0xffffffffu, a, o);
    if (t == 0) red[0] = a;
    __syncthreads();
    float mu = red[0] * (1.0f / DIMX);
    float d  = val - mu;
    sm[t] = d * d;
    __syncthreads();
    float b = 0.f;
    if (t < 32) b = sm[t] + sm[t+32] + sm[t+64];
    #pragma unroll
    for (int o = 16; o > 0; o >>= 1) b += __shfl_down_sync(0xffffffffu, b, o);
    if (t == 0) red[1] = b;
    __syncthreads();
    float var = red[1] * (1.0f / DIMX);
    float lnv = d * rsqrtf(var + EPSX) * (g[t] + 1.0f);
    if (REPLACE) {
        x[idx] = lnv;
    } else {
        x[idx] = val;
        if (BFOUT) ((bf16*)outp)[idx] = __float2bfloat16_rn(lnv);
        else       ((float*)outp)[idx] = lnv;
    }
}

// ---------------- row softmax over 512 cols (bf16 in/out, fp32 math) ----------------
__global__ void softmax_kernel(bf16* __restrict__ sim) {
    int row = blockIdx.x;
    bf16* p = sim + (size_t)row * NSEQ;
    int t = threadIdx.x;                    // 256
    float a = __bfloat162float(p[t]), b = __bfloat162float(p[t + 256]);
    __shared__ float s[256];
    s[t] = fmaxf(a, b);
    __syncthreads();
    for (int o = 128; o >= 32; o >>= 1) { if (t < o) s[t] = fmaxf(s[t], s[t+o]); __syncthreads(); }
    if (t < 32) {
        float x = s[t];
        #pragma unroll
        for (int o = 16; o > 0; o >>= 1) x = fmaxf(x, __shfl_down_sync(0xffffffffu, x, o));
        if (t == 0) s[0] = x;
    }
    __syncthreads();
    float m = s[0];
    __syncthreads();
    float ea = expf(a - m), eb = expf(b - m);
    s[t] = ea + eb;
    __syncthreads();
    for (int o = 128; o >= 32; o >>= 1) { if (t < o) s[t] += s[t+o]; __syncthreads(); }
    if (t < 32) {
        float x = s[t];
        #pragma unroll
        for (int o = 16; o > 0; o >>= 1) x += __shfl_down_sync(0xffffffffu, x, o);
        if (t == 0) s[0] = x;
    }
    __syncthreads();
    float inv = 1.0f / s[0];
    p[t]       = __float2bfloat16_rn(ea * inv);
    p[t + 256] = __float2bfloat16_rn(eb * inv);
}

// ---------------- bf16 tensor-core GEMM, 4-stage cp.async, single sync/tile ----------------
// 128x128 block, BK=32, 256 threads, warp tile 64x32, m16n8k16.
// A: row-major bf16 [M,K].
// B NN: pair-interleaved words [K/2][N] (uint32 = bf16x2 along k); ldb/strides in WORDS.
// B TRANSB: row-major bf16 [N,K]; ldb/strides in bf16 elements.
// OUT: 0 = fp32 plain (split partials), 1 = bf16 plain, 2 = QKV (bf16 qk + v interleaved).
template<bool TRANSB, bool BIAS, bool GELU, bool SPLIT, int OUT>
__global__ __launch_bounds__(256, 2)
void mma_gemm(const bf16* __restrict__ A, const void* __restrict__ Bm,
              const float* __restrict__ bias, void* __restrict__ Cp,
              uint32_t* __restrict__ Cv,
              int M, int Nn, int K_len,
              int lda, int ldb, int ldc,
              long sA_b, long sA_h, long sB_b, long sB_h, long sC_b, long sC_h,
              long splitStride, float alpha) {
    extern __shared__ bf16 smem[];
    bf16* Asm = smem;                      // [STAGES][128][40]
    bf16* Bsm = smem + STAGES*A_STG;

    const int tid = threadIdx.x;
    const int bz  = blockIdx.z;
    const bf16* Ab; const void* Bb;
    long coff;
    int kbase;
    if (SPLIT) {
        Ab = A; Bb = Bm;
        coff = (long)bz * splitStride;
        kbase = bz * K_len;
    } else {
        long bb = bz >> 3, hh = bz & 7;
        Ab = A + bb * sA_b + hh * sA_h;
        if (TRANSB) Bb = (const void*)((const bf16*)Bm + bb * sB_b + hh * sB_h);
        else        Bb = (const void*)((const uint32_t*)Bm + bb * sB_b + hh * sB_h);
        coff = bb * sC_b + hh * sC_h;
        kbase = 0;
    }

    const int bm = blockIdx.y * 128;
    const int bn = blockIdx.x * 128;
    const int wid = tid >> 5;
    const int lane = tid & 31;
    const int gid = lane >> 2;
    const int tg  = lane & 3;
    const int wm = (wid & 1) * 64;
    const int wn = (wid >> 1) * 32;

    const uint32_t as0 = (uint32_t)__cvta_generic_to_shared(Asm);
    const uint32_t bs0 = (uint32_t)__cvta_generic_to_shared(Bsm);

    const int nt = K_len / 32;

    float acc[4][4][4];
    #pragma unroll
    for (int mi = 0; mi < 4; mi++)
        #pragma unroll
        for (int ni = 0; ni < 4; ni++)
            #pragma unroll
            for (int r = 0; r < 4; r++) acc[mi][ni][r] = 0.f;

    auto load_tile = [&](int t, int s) {
        const int kpos = kbase + t * 32;
        // A: 128 rows x 32 bf16, 4 chunks/row of 8 bf16
        #pragma unroll
        for (int r = 0; r < 2; r++) {
            int idx = tid + 256 * r;
            int row = idx >> 2;
            int kc  = (idx & 3) * 8;
            const bf16* src = Ab + (size_t)(bm + row) * lda + kpos + kc;
            cp16(as0 + (s * A_STG + row * 40 + kc) * 2, src, true);
        }
        if (!TRANSB) {
            // B: 16 pair-rows x 128 words
            const uint32_t* Bw = (const uint32_t*)Bb;
            int kp0 = kpos >> 1;
            #pragma unroll
            for (int r = 0; r < 2; r++) {
                int idx = tid + 256 * r;
                int wrow = idx >> 5;
                int wc   = (idx & 31) * 4;
                const uint32_t* src = Bw + (size_t)(kp0 + wrow) * ldb + bn + wc;
                cp16(bs0 + (s * B_STGW + wrow * 136 + wc) * 4, src, (bn + wc) < Nn);
            }
        } else {
            const bf16* Bt = (const bf16*)Bb;
            #pragma unroll
            for (int r = 0; r < 2; r++) {
                int idx = tid + 256 * r;
                int row = idx >> 2;
                int kc  = (idx & 3) * 8;
                const bf16* src = Bt + (size_t)(bn + row) * ldb + kpos + kc;
                cp16(bs0 + (s * A_STG + row * 40 + kc) * 2, src, (bn + row) < Nn);
            }
        }
        cp_commit();
    };

    #pragma unroll
    for (int s = 0; s < STAGES - 1; s++)
        if (s < nt) load_tile(s, s);

    for (int t = 0; t < nt; t++) {
        const int cur = t & 3;
        if (t + 3 <= nt)      cp_wait<2>();
        else if (t + 2 <= nt) cp_wait<1>();
        else                  cp_wait<0>();
        __syncthreads();
        if (t + 3 < nt) load_tile(t + 3, (t + 3) & 3);

        const bf16* as = Asm + cur * A_STG;
        const bf16* bt = Bsm + cur * A_STG;
        const uint32_t* bw = (const uint32_t*)Bsm + cur * B_STGW;

        #pragma unroll
        for (int s = 0; s < 32; s += 16) {
            // B fragments: bf[ni][0..1]
            uint32_t bf[4][2];
            if (!TRANSB) {
                #pragma unroll
                for (int ni = 0; ni < 4; ni++) {
                    int ncol = wn + ni * 8 + gid;
                    bf[ni][0] = bw[((s >> 1) + tg    ) * 136 + ncol];
                    bf[ni][1] = bw[((s >> 1) + tg + 4) * 136 + ncol];
                }
            } else {
                #pragma unroll
                for (int ni = 0; ni < 4; ni++) {
                    int ncol = wn + ni * 8 + gid;
                    bf[ni][0] = *(const uint32_t*)(bt + ncol * 40 + s + 2*tg);
                    bf[ni][1] = *(const uint32_t*)(bt + ncol * 40 + s + 2*tg + 8);
                }
            }
            #pragma unroll
            for (int mi = 0; mi < 4; mi++) {
                int mrow = wm + mi * 16 + gid;
                uint32_t a0 = *(const uint32_t*)(as + (mrow    ) * 40 + s + 2*tg);
                uint32_t a1 = *(const uint32_t*)(as + (mrow + 8) * 40 + s + 2*tg);
                uint32_t a2 = *(const uint32_t*)(as + (mrow    ) * 40 + s + 2*tg + 8);
                uint32_t a3 = *(const uint32_t*)(as + (mrow + 8) * 40 + s + 2*tg + 8);
                #pragma unroll
                for (int ni = 0; ni < 4; ni++)
                    mma_bf16(acc[mi][ni][0], acc[mi][ni][1], acc[mi][ni][2], acc[mi][ni][3],
                             a0, a1, a2, a3, bf[ni][0], bf[ni][1]);
            }
        }
    }

    // ---- epilogue (M multiple of 128; guard N)
    #pragma unroll
    for (int mi = 0; mi < 4; mi++) {
        int m0 = bm + wm + mi * 16 + gid;
        #pragma unroll
        for (int ni = 0; ni < 4; ni++) {
            int n0 = bn + wn + ni * 8 + tg * 2;
            #pragma unroll
            for (int rr = 0; rr < 2; rr++) {
                int m = m0 + rr * 8;
                #pragma unroll
                for (int cc = 0; cc < 2; cc++) {
                    int n = n0 + cc;
                    if (n < Nn) {
                        float v = acc[mi][ni][rr * 2 + cc] * alpha;
                        if (BIAS) v += bias[n];
                        if (GELU) v = 0.5f * v * (1.0f + erff(v * 0.70710678118654752f));
                        if (OUT == 0) {
                            ((float*)Cp)[coff + (size_t)m * ldc + n] = v;
                        } else if (OUT == 1) {
                            ((bf16*)Cp)[coff + (size_t)m * ldc + n] = __float2bfloat16_rn(v);
                        } else {
                            if (n < 2*INNERX) {
                                ((bf16*)Cp)[coff + (size_t)m * ldc + n] = __float2bfloat16_rn(v);
                            } else {
                                int c = n - 2*INNERX;
                                size_t vi = ((size_t)(m >> 1) * INNERX + c) * 2 + (m & 1);
                                ((bf16*)Cv)[vi] = __float2bfloat16_rn(v);
                            }
                        }
                    }
                }
            }
        }
    }
}

// ---------------- host orchestration ----------------
extern "C" void kernel_launch(void* const* d_in, const int* in_sizes, int n_in,
                              void* d_out, int out_size) {
    const float* x         = (const float*)d_in[0];
    const float* gam_a     = (const float*)d_in[1];
    const float* Wq        = (const float*)d_in[2];
    const float* Wk        = (const float*)d_in[3];
    const float* Wv        = (const float*)d_in[4];
    const float* Wo        = (const float*)d_in[5];
    const float* gam_m     = (const float*)d_in[6];
    const float* W1        = (const float*)d_in[7];
    const float* b1        = (const float*)d_in[8];
    const float* W2        = (const float*)d_in[9];
    const float* b2        = (const float*)d_in[10];
    const float* gam_mid   = (const float*)d_in[11];
    const float* gam_final = (const float*)d_in[12];
    float* out = (float*)d_out;

    float *px, *ppart;
    bf16 *ph, *pqk, *po, *psim, *pmh;
    uint32_t *pv, *pwqkv, *pwo, *pw1, *pw2;
    cudaGetSymbolAddress((void**)&px,    g_x);
    cudaGetSymbolAddress((void**)&ph,    g_h);
    cudaGetSymbolAddress((void**)&pqk,   g_qk);
    cudaGetSymbolAddress((void**)&pv,    g_v);
    cudaGetSymbolAddress((void**)&po,    g_o);
    cudaGetSymbolAddress((void**)&psim,  g_sim);
    cudaGetSymbolAddress((void**)&pmh,   g_mh);
    cudaGetSymbolAddress((void**)&ppart, g_part);
    cudaGetSymbolAddress((void**)&pwqkv, g_wqkv);
    cudaGetSymbolAddress((void**)&pwo,   g_wo);
    cudaGetSymbolAddress((void**)&pw1,   g_w1);
    cudaGetSymbolAddress((void**)&pw2,   g_w2);

    cudaFuncSetAttribute(mma_gemm<false,false,false,false,2>,
                         cudaFuncAttributeMaxDynamicSharedMemorySize, SMEM_BYTES);
    cudaFuncSetAttribute(mma_gemm<true,false,false,false,1>,
                         cudaFuncAttributeMaxDynamicSharedMemorySize, SMEM_BYTES);
    cudaFuncSetAttribute(mma_gemm<false,false,false,false,1>,
                         cudaFuncAttributeMaxDynamicSharedMemorySize, SMEM_BYTES);
    cudaFuncSetAttribute(mma_gemm<false,false,false,true,0>,
                         cudaFuncAttributeMaxDynamicSharedMemorySize, SMEM_BYTES);
    cudaFuncSetAttribute(mma_gemm<false,true,true,false,1>,
                         cudaFuncAttributeMaxDynamicSharedMemorySize, SMEM_BYTES);

    // ---- weight packing (bf16 pair-interleaved words) ----
    {
        int nq = 15*(DIMX/2)*NQKV;
        pack_qkv_kernel<<<(nq + 255)/256, 256>>>(Wq, Wk, Wv, pwqkv, nq);
        int no = 15*(INNERX/2)*DIMX;
        pack_pairs_kernel<<<(no + 255)/256, 256>>>(Wo, pwo, DIMX, no);
        int n1 = 10*(DIMX/2)*HIDX;
        pack_pairs_kernel<<<(n1 + 255)/256, 256>>>(W1, pw1, HIDX, n1);
        int n2 = 10*(HIDX/2)*DIMX;
        pack_pairs_kernel<<<(n2 + 255)/256, 256>>>(W2, pw2, DIMX, n2);
    }

    copy_kernel<<<(ROWSX*DIMX + 255)/256, 256>>>(x, px, ROWSX*DIMX);
    ln_kernel<<<ROWSX, DIMX>>>(px, gam_a + 0, ph);

    const long sQK_b  = (long)NSEQ * 2*INNERX;     // qk activations (bf16 elems)
    const long sQK_h  = DHX;
    const long sV_b   = (long)(NSEQ/2) * INNERX;   // v words
    const long sV_h   = DHX;
    const long sSIM_h = (long)NSEQ * NSEQ;
    const long sSIM_b = sSIM_h * HEADSX;
    const long sO_b   = (long)NSEQ * INNERX;
    const long sO_h   = DHX;

    auto do_attn = [&](int widx) {
        const uint32_t* wqkv_l = pwqkv + (size_t)widx * (DIMX/2) * NQKV;
        const uint32_t* wo_l   = pwo   + (size_t)widx * (INNERX/2) * DIMX;
        // fused QKV: [1024,96] @ [96,18432]; q,k -> pqk; v -> interleaved pv
        mma_gemm<false,false,false,false,2><<<dim3(NQKV/128, ROWSX/128, 1), 256, SMEM_BYTES>>>(
            ph, wqkv_l, nullptr, pqk, pv, ROWSX, NQKV, DIMX, DIMX, NQKV, 2*INNERX,
            0,0,0,0,0,0, 0, 1.0f);
        // scores = SCALE * q @ k^T per (b,h)  [TRANSB: B = k rows, bf16]
        mma_gemm<true,false,false,false,1><<<dim3(NSEQ/128, NSEQ/128, BX*HEADSX), 256, SMEM_BYTES>>>(
            pqk, pqk + INNERX, nullptr, psim, nullptr, NSEQ, NSEQ, DHX,
            2*INNERX, 2*INNERX, NSEQ,
            sQK_b, sQK_h, sQK_b, sQK_h, sSIM_b, sSIM_h, 0, SCALEX);
        softmax_kernel<<<BX*HEADSX*NSEQ, 256>>>(psim);
        // context = a @ v per (b,h); B = v interleaved words
        mma_gemm<false,false,false,false,1><<<dim3(DHX/128, NSEQ/128, BX*HEADSX), 256, SMEM_BYTES>>>(
            psim, pv, nullptr, po, nullptr, NSEQ, DHX, NSEQ,
            NSEQ, INNERX /*words*/, INNERX,
            sSIM_b, sSIM_h, sV_b, sV_h, sO_b, sO_h, 0, 1.0f);
        // Wo split-K partials (fp32)
        mma_gemm<false,false,false,true,0><<<dim3(1, ROWSX/128, SPLIT_WO), 256, SMEM_BYTES>>>(
            po, wo_l, nullptr, ppart, nullptr, ROWSX, DIMX, INNERX/SPLIT_WO,
            INNERX, DIMX /*words*/, DIMX,
            0,0,0,0,0,0, (long)ROWSX*DIMX, 1.0f);
    };
    auto do_mlp_gemms = [&](int midx) {
        const uint32_t* w1_l = pw1 + (size_t)midx * (DIMX/2) * HIDX;
        const uint32_t* w2_l = pw2 + (size_t)midx * (HIDX/2) * DIMX;
        mma_gemm<false,true,true,false,1><<<dim3(HIDX/128, ROWSX/128, 1), 256, SMEM_BYTES>>>(
            ph, w1_l, b1 + (size_t)midx * HIDX, pmh, nullptr, ROWSX, HIDX, DIMX,
            DIMX, HIDX /*words*/, HIDX,
            0,0,0,0,0,0, 0, 1.0f);
        mma_gemm<false,false,false,true,0><<<dim3(1, ROWSX/128, SPLIT_W2), 256, SMEM_BYTES>>>(
            pmh, w2_l, nullptr, ppart, nullptr, ROWSX, DIMX, HIDX/SPLIT_W2,
            HIDX, DIMX /*words*/, DIMX,
            0,0,0,0,0,0, (long)ROWSX*DIMX, 1.0f);
    };

    for (int d = 0; d < DEPTHX; d++) {
        do_attn(3*d + 0);
        red_ln_kernel<true,false,false><<<ROWSX, DIMX>>>(
            ppart, SPLIT_WO, nullptr, px, gam_m + (size_t)(2*d+0)*DIMX, ph);
        do_mlp_gemms(2*d + 0);
        red_ln_kernel<true,false,true><<<ROWSX, DIMX>>>(
            ppart, SPLIT_W2, b2 + (size_t)(2*d+0)*DIMX, px, gam_a + (size_t)(3*d+1)*DIMX, ph);
        do_attn(3*d + 1);
        red_ln_kernel<true,false,false><<<ROWSX, DIMX>>>(
            ppart, SPLIT_WO, nullptr, px, gam_a + (size_t)(3*d+2)*DIMX, ph);
        do_attn(3*d + 2);
        red_ln_kernel<true,true,false><<<ROWSX, DIMX>>>(
            ppart, SPLIT_WO, nullptr, px, gam_mid + (size_t)d*DIMX, nullptr);
        ln_kernel<<<ROWSX, DIMX>>>(px, gam_m + (size_t)(2*d+1)*DIMX, ph);
        do_mlp_gemms(2*d + 1);
        if (d < DEPTHX - 1) {
            red_ln_kernel<true,false,true><<<ROWSX, DIMX>>>(
                ppart, SPLIT_W2, b2 + (size_t)(2*d+1)*DIMX, px, gam_a + (size_t)(3*d+3)*DIMX, ph);
        } else {
            red_ln_kernel<false,false,true><<<ROWSX, DIMX>>>(
                ppart, SPLIT_W2, b2 + (size_t)(2*d+1)*DIMX, px, gam_final, out);
        }
    }
}